// round 14
// baseline (speedup 1.0000x reference)
#include <cuda_runtime.h>

#define BB   8
#define CIN  32
#define COUT 32
#define HH   128
#define WW   128
#define SS   1024
#define JJ   (HH*WW)

// Half-task partials: slot g = (b*32+i)*2 + half. Fully overwritten each launch.
__device__ float g_Th[BB*CIN*2];
__device__ float g_Uh[BB*CIN*2];
__device__ float g_Vh[BB*CIN*2];

// ---------------------------------------------------------------------------
// Kernel A: 512 blocks; block g = half-task (bi = g>>1, half = g&1).
// Each block reduces 512 samples (2 per thread) of one (b,i) plane.
// ---------------------------------------------------------------------------
__global__ void __launch_bounds__(256) nystrom_reduce_tuv(
    const float* __restrict__ v,
    const int*   __restrict__ idx32)   // int32 or int64 (detected)
{
    const int g    = blockIdx.x;           // 0..511
    const int bi   = g >> 1;               // b*32 + i
    const int half = g & 1;
    const float* plane = v + (size_t)bi * JJ;
    const int tid  = threadIdx.x;
    const int lane = tid & 31;
    const int warp = tid >> 5;

    // indices are a permutation (distinct); three zeros at int32 positions
    // 1,3,5 can only be int64 high-halves.
    const bool is64 = (idx32[1] == 0) && (idx32[3] == 0) && (idx32[5] == 0);

    const float step = 2.0f / 127.0f;
    float t = 0.f, u = 0.f, w = 0.f;

    #pragma unroll
    for (int k = 0; k < 2; ++k) {
        const int s = half * 512 + tid + k * 256;
        const int j = is64 ? idx32[2 * s] : idx32[s];
        const float x = -1.0f + step * (float)(j & (WW - 1));
        const float y = -1.0f + step * (float)(j >> 7);
        const float val = __ldg(plane + j);
        t += val;
        u  = fmaf(x, val, u);
        w  = fmaf(y, val, w);
    }

    #pragma unroll
    for (int off = 16; off > 0; off >>= 1) {
        t += __shfl_down_sync(0xffffffffu, t, off);
        u += __shfl_down_sync(0xffffffffu, u, off);
        w += __shfl_down_sync(0xffffffffu, w, off);
    }
    __shared__ float sred[3][8];
    if (lane == 0) { sred[0][warp] = t; sred[1][warp] = u; sred[2][warp] = w; }
    __syncthreads();
    if (warp == 0) {
        float T = (lane < 8) ? sred[0][lane] : 0.f;
        float U = (lane < 8) ? sred[1][lane] : 0.f;
        float V = (lane < 8) ? sred[2][lane] : 0.f;
        #pragma unroll
        for (int off = 4; off > 0; off >>= 1) {
            T += __shfl_down_sync(0xffffffffu, T, off);
            U += __shfl_down_sync(0xffffffffu, U, off);
            V += __shfl_down_sync(0xffffffffu, V, off);
        }
        if (lane == 0) { g_Th[g] = T; g_Uh[g] = U; g_Vh[g] = V; }
    }
    __syncthreads();

#if defined(__CUDA_ARCH__) && (__CUDA_ARCH__ >= 900)
    __threadfence();
    cudaTriggerProgrammaticLaunchCompletion();
#endif
}

// ---------------------------------------------------------------------------
// Kernel B: output fill — R6 config (best measured: 6.88us).
// 4 blocks per (b,o) plane; 4 float4 per thread. Warp dot sums the two halves.
// ---------------------------------------------------------------------------
__global__ void __launch_bounds__(256) nystrom_fill(
    const float* __restrict__ weight,   // [COUT, CIN, 2]
    float*       __restrict__ out)      // [B, COUT, H, W]
{
    const int plane = blockIdx.x >> 2;   // b*32 + o
    const int chunk = blockIdx.x & 3;    // 4096-float chunk within plane
    const int b = plane >> 5;
    const int o = plane & 31;
    const int tid  = threadIdx.x;
    const int lane = tid & 31;

    // Weight load + setup overlap kernel A under PDL.
    const float2 wv = ((const float2*)weight)[o * CIN + lane];
    const float step = 2.0f / 127.0f;

#if defined(__CUDA_ARCH__) && (__CUDA_ARCH__ >= 900)
    cudaGridDependencySynchronize();
#endif

    // Warp-parallel dot: lane = channel; sum the two half-task partials.
    const int hbase = (b * CIN + lane) * 2;
    const float T = __ldcg(g_Th + hbase) + __ldcg(g_Th + hbase + 1);
    const float U = __ldcg(g_Uh + hbase) + __ldcg(g_Uh + hbase + 1);
    const float V = __ldcg(g_Vh + hbase) + __ldcg(g_Vh + hbase + 1);

    float p = T * wv.x;
    float q = T * wv.y;
    float r = fmaf(U, wv.x, V * wv.y);
    #pragma unroll
    for (int off = 16; off > 0; off >>= 1) {
        p += __shfl_xor_sync(0xffffffffu, p, off);
        q += __shfl_xor_sync(0xffffffffu, q, off);
        r += __shfl_xor_sync(0xffffffffu, r, off);
    }
    const float P = p, Q = q, R = r;

    float4* outp = (float4*)(out + (size_t)plane * JJ + chunk * 4096);

    #pragma unroll
    for (int k = 0; k < 4; ++k) {
        const int q4 = tid + k * 256;          // float4 index within chunk
        const int rr = chunk * 4096 + q4 * 4;  // linear index within plane
        const int h  = rr >> 7;
        const int wq = rr & (WW - 1);
        const float y = -1.0f + step * (float)h;
        const float base = fmaf(y, Q, -R);
        const float x0 = -1.0f + step * (float)wq;
        float4 o4;
        o4.x = fmaf(x0,               P, base);
        o4.y = fmaf(x0 +        step, P, base);
        o4.z = fmaf(x0 + 2.0f * step, P, base);
        o4.w = fmaf(x0 + 3.0f * step, P, base);
        outp[q4] = o4;
    }
}

extern "C" void kernel_launch(void* const* d_in, const int* in_sizes, int n_in,
                              void* d_out, int out_size)
{
    const float* v      = (const float*)d_in[0];
    const float* weight = (const float*)d_in[1];
    const int*   idx32  = (const int*)  d_in[2];
    float*       out    = (float*)d_out;

    nystrom_reduce_tuv<<<BB * CIN * 2, 256>>>(v, idx32);

    cudaLaunchConfig_t cfg = {};
    cfg.gridDim  = dim3(BB * COUT * 4);   // 1024 blocks (R6 fill config)
    cfg.blockDim = dim3(256);
    cfg.dynamicSmemBytes = 0;
    cfg.stream = 0;
    cudaLaunchAttribute attr[1];
    attr[0].id = cudaLaunchAttributeProgrammaticStreamSerialization;
    attr[0].val.programmaticStreamSerializationAllowed = 1;
    cfg.attrs = attr;
    cfg.numAttrs = 1;
    cudaLaunchKernelEx(&cfg, nystrom_fill, weight, (float*)out);
}

// round 15
// speedup vs baseline: 1.4060x; 1.4060x over previous
#include <cuda_runtime.h>

#define BB   8
#define CIN  32
#define COUT 32
#define HH   128
#define WW   128
#define SS   1024
#define JJ   (HH*WW)

// Scratch: fully overwritten every launch (deterministic across graph replays).
__device__ float g_T[BB*CIN];
__device__ float g_U[BB*CIN];
__device__ float g_V[BB*CIN];

// ---------------------------------------------------------------------------
// Kernel A: one block per (b,i). T/U/V gather-reductions. (R6 exact, proven.)
// ---------------------------------------------------------------------------
__global__ void __launch_bounds__(256) nystrom_reduce_tuv(
    const float* __restrict__ v,
    const int*   __restrict__ idx32)   // int32 or int64 (detected)
{
    const int bi  = blockIdx.x;            // b*32 + i
    const float* plane = v + (size_t)bi * JJ;
    const int tid  = threadIdx.x;
    const int lane = tid & 31;
    const int warp = tid >> 5;

    // indices are a permutation (distinct); three zeros at int32 positions
    // 1,3,5 can only be int64 high-halves.
    const bool is64 = (idx32[1] == 0) && (idx32[3] == 0) && (idx32[5] == 0);

    const float step = 2.0f / 127.0f;
    float t = 0.f, u = 0.f, w = 0.f;

    #pragma unroll
    for (int k = 0; k < 4; ++k) {
        const int s = tid + k * 256;
        const int j = is64 ? idx32[2 * s] : idx32[s];
        const float x = -1.0f + step * (float)(j & (WW - 1));
        const float y = -1.0f + step * (float)(j >> 7);
        const float val = __ldg(plane + j);
        t += val;
        u  = fmaf(x, val, u);
        w  = fmaf(y, val, w);
    }

    #pragma unroll
    for (int off = 16; off > 0; off >>= 1) {
        t += __shfl_down_sync(0xffffffffu, t, off);
        u += __shfl_down_sync(0xffffffffu, u, off);
        w += __shfl_down_sync(0xffffffffu, w, off);
    }
    __shared__ float sred[3][8];
    if (lane == 0) { sred[0][warp] = t; sred[1][warp] = u; sred[2][warp] = w; }
    __syncthreads();
    if (warp == 0) {
        float T = (lane < 8) ? sred[0][lane] : 0.f;
        float U = (lane < 8) ? sred[1][lane] : 0.f;
        float V = (lane < 8) ? sred[2][lane] : 0.f;
        #pragma unroll
        for (int off = 4; off > 0; off >>= 1) {
            T += __shfl_down_sync(0xffffffffu, T, off);
            U += __shfl_down_sync(0xffffffffu, U, off);
            V += __shfl_down_sync(0xffffffffu, V, off);
        }
        if (lane == 0) { g_T[bi] = T; g_U[bi] = U; g_V[bi] = V; }
    }
    __syncthreads();

#if defined(__CUDA_ARCH__) && (__CUDA_ARCH__ >= 900)
    __threadfence();
    cudaTriggerProgrammaticLaunchCompletion();
#endif
}

// ---------------------------------------------------------------------------
// Kernel B: output fill, ONE-WAVE geometry: 256 blocks x 1024 threads
// (262K threads ~= single co-resident wave). One plane per block; every warp
// computes the P/Q/R dot redundantly (lane = channel, no smem/barrier);
// 4 STG.128 per thread.
// ---------------------------------------------------------------------------
__global__ void __launch_bounds__(1024) nystrom_fill(
    const float* __restrict__ weight,   // [COUT, CIN, 2]
    float*       __restrict__ out)      // [B, COUT, H, W]
{
    const int plane = blockIdx.x;        // b*32 + o
    const int b = plane >> 5;
    const int o = plane & 31;
    const int tid  = threadIdx.x;
    const int lane = tid & 31;

    // Weight load + setup overlap kernel A under PDL.
    const float2 wv = ((const float2*)weight)[o * CIN + lane];
    const float step = 2.0f / 127.0f;

#if defined(__CUDA_ARCH__) && (__CUDA_ARCH__ >= 900)
    cudaGridDependencySynchronize();
#endif

    // Warp-parallel dot: lane = channel. L2 loads (bypass possibly-stale L1).
    const float T = __ldcg(g_T + b * CIN + lane);
    const float U = __ldcg(g_U + b * CIN + lane);
    const float V = __ldcg(g_V + b * CIN + lane);

    float p = T * wv.x;
    float q = T * wv.y;
    float r = fmaf(U, wv.x, V * wv.y);
    #pragma unroll
    for (int off = 16; off > 0; off >>= 1) {
        p += __shfl_xor_sync(0xffffffffu, p, off);
        q += __shfl_xor_sync(0xffffffffu, q, off);
        r += __shfl_xor_sync(0xffffffffu, r, off);
    }
    const float P = p, Q = q, R = r;

    float4* outp = (float4*)(out + (size_t)plane * JJ);

    #pragma unroll
    for (int k = 0; k < 4; ++k) {
        const int q4 = tid + k * 1024;         // float4 index in plane [0,4096)
        const int rr = q4 * 4;                 // linear index within plane
        const int h  = rr >> 7;
        const int wq = rr & (WW - 1);
        const float y = -1.0f + step * (float)h;
        const float base = fmaf(y, Q, -R);
        const float x0 = -1.0f + step * (float)wq;
        float4 o4;
        o4.x = fmaf(x0,               P, base);
        o4.y = fmaf(x0 +        step, P, base);
        o4.z = fmaf(x0 + 2.0f * step, P, base);
        o4.w = fmaf(x0 + 3.0f * step, P, base);
        outp[q4] = o4;
    }
}

extern "C" void kernel_launch(void* const* d_in, const int* in_sizes, int n_in,
                              void* d_out, int out_size)
{
    const float* v      = (const float*)d_in[0];
    const float* weight = (const float*)d_in[1];
    const int*   idx32  = (const int*)  d_in[2];
    float*       out    = (float*)d_out;

    nystrom_reduce_tuv<<<BB * CIN, 256>>>(v, idx32);

    cudaLaunchConfig_t cfg = {};
    cfg.gridDim  = dim3(BB * COUT);       // 256 blocks, one plane each
    cfg.blockDim = dim3(1024);
    cfg.dynamicSmemBytes = 0;
    cfg.stream = 0;
    cudaLaunchAttribute attr[1];
    attr[0].id = cudaLaunchAttributeProgrammaticStreamSerialization;
    attr[0].val.programmaticStreamSerializationAllowed = 1;
    cfg.attrs = attr;
    cfg.numAttrs = 1;
    cudaLaunchKernelEx(&cfg, nystrom_fill, weight, (float*)out);
}